// round 2
// baseline (speedup 1.0000x reference)
#include <cuda_runtime.h>

#define BATCH 512
#define DLAT  32
#define ACT   18
#define FED   128
#define AED   64
#define VD    192
#define KDIM  192
#define HID   256
#define NH    32

// ---------------- scratch (static device allocations only) ----------------
__device__ float g_w[BATCH * DLAT];                    // softmax weights [b][d]
__device__ float g_ae[BATCH * AED];                    // action embeds  [b][j]
__device__ float g_G[NH * DLAT * HID];                 // [h][d][k]
__device__ float g_c0[NH * HID];                       // [h][k]
__device__ float g_pooled[(size_t)NH * BATCH * HID];   // [h][b][k]  16MB

// ============================================================================
// K1: per-batch prep: queries, action embeds, scores, softmax, attn_weights
// grid = B blocks, 192 threads
// ============================================================================
__global__ void k_prep(const float* __restrict__ feat, const float* __restrict__ act,
                       const float* __restrict__ Wq,   const float* __restrict__ bq,
                       const float* __restrict__ Wk,   const float* __restrict__ bk,
                       const float* __restrict__ Wav,  const float* __restrict__ bav,
                       float* __restrict__ out_attnw)
{
    int b = blockIdx.x;
    int t = threadIdx.x;
    __shared__ float a_s[ACT];
    __shared__ float q_s[KDIM];
    __shared__ float s1_s[DLAT];
    __shared__ float w_s[DLAT];
    __shared__ float s0_s;

    if (t < ACT) a_s[t] = act[b * ACT + t];
    __syncthreads();

    // queries[b,t] = a @ Wq + bq   (t < 192 always, blockDim=192)
    float q = bq[t];
#pragma unroll
    for (int i = 0; i < ACT; i++) q = fmaf(a_s[i], Wq[i * KDIM + t], q);
    q_s[t] = q;

    // action embeds (t < 64)
    if (t < AED) {
        float e = bav[t];
#pragma unroll
        for (int i = 0; i < ACT; i++) e = fmaf(a_s[i], Wav[i * AED + t], e);
        g_ae[b * AED + t] = e;
    }
    __syncthreads();

    // s1[d] = Wk[d,:] . q  ;  s0 = bk . q
    if (t < DLAT) {
        const float* wk = Wk + t * KDIM;
        float s = 0.f;
        for (int j = 0; j < KDIM; j++) s = fmaf(wk[j], q_s[j], s);
        s1_s[t] = s;
    } else if (t == DLAT) {
        float s = 0.f;
        for (int j = 0; j < KDIM; j++) s = fmaf(bk[j], q_s[j], s);
        s0_s = s;
    }
    __syncthreads();

    // softmax over d (warp 0)
    if (t < 32) {
        const float inv = 0.07216878364870323f; // 1/sqrt(192)
        float sc = (feat[b * DLAT + t] * s1_s[t] + s0_s) * inv;
        float m = sc;
#pragma unroll
        for (int o = 16; o > 0; o >>= 1) m = fmaxf(m, __shfl_xor_sync(0xffffffffu, m, o));
        float e = __expf(sc - m);
        float s = e;
#pragma unroll
        for (int o = 16; o > 0; o >>= 1) s += __shfl_xor_sync(0xffffffffu, s, o);
        float w = e / s;
        w_s[t] = w;
        g_w[b * DLAT + t] = w;
    }
    __syncthreads();

    // attn_weights[b,h,d] = w[b,d] broadcast over h
    for (int idx = t; idx < NH * DLAT; idx += blockDim.x)
        out_attnw[(size_t)b * NH * DLAT + idx] = w_s[idx & (DLAT - 1)];
}

// ============================================================================
// K2: precompute G[h,d,k] = Wfv[d,:] @ W1[h,:128,k]   and
//                c0[h,k]  = bfv @ W1[h,:128,k] + b1[h,k]
// grid = (2 k-chunks of 128, NH), 256 threads
// ============================================================================
__global__ __launch_bounds__(256)
void k_gpre(const float* __restrict__ Wfv, const float* __restrict__ bfv,
            const float* __restrict__ W1,  const float* __restrict__ b1)
{
    int h = blockIdx.y;
    int kbase = blockIdx.x * 128;
    int t = threadIdx.x;

    extern __shared__ float sm2[];
    float* W1s   = sm2;                 // [128 f][128 kk]
    float* Wfv_s = W1s + FED * 128;     // [32 d][128 f]
    float* bfv_s = Wfv_s + DLAT * FED;  // [128]

    const float* W1h = W1 + (size_t)h * VD * HID;
    for (int idx = t; idx < FED * 128; idx += 256) {
        int f = idx >> 7, kk = idx & 127;
        W1s[f * 128 + kk] = W1h[f * HID + kbase + kk];
    }
    for (int idx = t; idx < DLAT * FED; idx += 256) Wfv_s[idx] = Wfv[idx];
    if (t < FED) bfv_s[t] = bfv[t];
    __syncthreads();

    int ty = t >> 5, tx = t & 31;
    int d0 = ty * 4;
    float acc[4][4] = {};
    for (int f = 0; f < FED; f++) {
        float w1r[4];
#pragma unroll
        for (int i = 0; i < 4; i++) w1r[i] = W1s[f * 128 + tx + 32 * i];
#pragma unroll
        for (int jj = 0; jj < 4; jj++) {
            float wv = Wfv_s[(d0 + jj) * FED + f];
#pragma unroll
            for (int i = 0; i < 4; i++) acc[jj][i] = fmaf(wv, w1r[i], acc[jj][i]);
        }
    }
#pragma unroll
    for (int jj = 0; jj < 4; jj++)
#pragma unroll
        for (int i = 0; i < 4; i++)
            g_G[((size_t)h * DLAT + d0 + jj) * HID + kbase + tx + 32 * i] = acc[jj][i];

    if (t < 128) {
        float c = b1[h * HID + kbase + t];
        for (int f = 0; f < FED; f++) c = fmaf(bfv_s[f], W1s[f * 128 + t], c);
        g_c0[h * HID + kbase + t] = c;
    }
}

// ============================================================================
// K4: pooled[h,b,k] = sum_d w[b,d] * relu( z[b,d]*G[h,d,k] + E[b,k] + c0[h,k] )
//     with E[b,k] = ae[b,:] @ W1[h,128:,k] computed in-block
// grid = (B/64, NH), 256 threads; each thread computes 8b x 8k outputs
// ============================================================================
#define BT4 64
__global__ __launch_bounds__(256)
void k_pool(const float* __restrict__ feat, const float* __restrict__ W1)
{
    int h  = blockIdx.y;
    int b0 = blockIdx.x * BT4;
    int t  = threadIdx.x;

    extern __shared__ float sm4[];
    float* G_s   = sm4;                  // 32*256
    float* c0_s  = G_s + DLAT * HID;     // 256
    float* W1a_s = c0_s + HID;           // 64*256
    float* ae_s  = W1a_s + AED * HID;    // 64*64
    float* z_s   = ae_s + BT4 * AED;     // 64*32
    float* w_s   = z_s + BT4 * DLAT;     // 64*32

    const float* W1ha = W1 + (size_t)h * VD * HID + (size_t)FED * HID;
    for (int idx = t; idx < DLAT * HID; idx += 256) G_s[idx] = g_G[(size_t)h * DLAT * HID + idx];
    for (int idx = t; idx < HID;        idx += 256) c0_s[idx] = g_c0[h * HID + idx];
    for (int idx = t; idx < AED * HID;  idx += 256) W1a_s[idx] = W1ha[idx];
    for (int idx = t; idx < BT4 * AED;  idx += 256) ae_s[idx] = g_ae[b0 * AED + idx];
    for (int idx = t; idx < BT4 * DLAT; idx += 256) z_s[idx]  = feat[b0 * DLAT + idx];
    for (int idx = t; idx < BT4 * DLAT; idx += 256) w_s[idx]  = g_w[b0 * DLAT + idx];
    __syncthreads();

    int tb = t >> 5, tk = t & 31;

    // e0 = E + c0
    float e0[8][8];
#pragma unroll
    for (int r = 0; r < 8; r++)
#pragma unroll
        for (int i = 0; i < 8; i++) e0[r][i] = c0_s[tk + 32 * i];

    for (int a = 0; a < AED; a++) {
        float w1a[8];
#pragma unroll
        for (int i = 0; i < 8; i++) w1a[i] = W1a_s[a * HID + tk + 32 * i];
#pragma unroll
        for (int r = 0; r < 8; r++) {
            float av = ae_s[(tb * 8 + r) * AED + a];
#pragma unroll
            for (int i = 0; i < 8; i++) e0[r][i] = fmaf(av, w1a[i], e0[r][i]);
        }
    }

    float acc[8][8] = {};
    for (int d = 0; d < DLAT; d++) {
        float gr[8];
#pragma unroll
        for (int i = 0; i < 8; i++) gr[i] = G_s[d * HID + tk + 32 * i];
#pragma unroll
        for (int r = 0; r < 8; r++) {
            float zz = z_s[(tb * 8 + r) * DLAT + d];
            float ww = w_s[(tb * 8 + r) * DLAT + d];
#pragma unroll
            for (int i = 0; i < 8; i++) {
                float v = fmaxf(fmaf(zz, gr[i], e0[r][i]), 0.f);
                acc[r][i] = fmaf(ww, v, acc[r][i]);
            }
        }
    }

    float* outp = g_pooled + (size_t)h * BATCH * HID + (size_t)b0 * HID;
#pragma unroll
    for (int r = 0; r < 8; r++)
#pragma unroll
        for (int i = 0; i < 8; i++)
            outp[(tb * 8 + r) * HID + tk + 32 * i] = acc[r][i];
}

// ============================================================================
// K5: attn_out = pooled @ W2 + b2 ; h2 = relu(attn_out @ W1o + b1o)
//     effect[b,h] = h2 . W2o[h] + b2o[h]
// grid = (B/64, NH), 256 threads (16x16), register-tiled GEMMs
// ============================================================================
#define BT5 64
__global__ __launch_bounds__(256)
void k_out(const float* __restrict__ W2,  const float* __restrict__ b2,
           const float* __restrict__ W1o, const float* __restrict__ b1o,
           const float* __restrict__ W2o, const float* __restrict__ b2o,
           float* __restrict__ effect)
{
    int h  = blockIdx.y;
    int b0 = blockIdx.x * BT5;
    int t  = threadIdx.x;

    extern __shared__ float sm5[];
    const int PSTR = HID + 1;                 // 257 (pad vs bank conflicts)
    float* P_s  = sm5;                        // pooled [64][257], reused for W1o chunks
    float* BUF  = P_s + BT5 * PSTR;           // W2 chunks [64][192] / attn_out [64][193]
    const int BUFSZ = 64 * 193;
    float* b2_s  = BUF + BUFSZ;               // 192
    float* b1o_s = b2_s + VD;                 // 256
    float* W2o_s = b1o_s + HID;               // 256

    const float* pin = g_pooled + (size_t)h * BATCH * HID + (size_t)b0 * HID;
    for (int idx = t; idx < BT5 * HID; idx += 256) {
        int bb = idx >> 8, k = idx & 255;
        P_s[bb * PSTR + k] = pin[idx];
    }
    for (int idx = t; idx < VD;  idx += 256) b2_s[idx] = b2[h * VD + idx];
    for (int idx = t; idx < HID; idx += 256) { b1o_s[idx] = b1o[h * HID + idx]; W2o_s[idx] = W2o[h * HID + idx]; }

    int ty = t >> 4, tx = t & 15;

    // ---- Stage B: attn_out[64][192] = P @ W2[h], k-chunked through smem ----
    float acc1[4][12] = {};
    const float* W2h = W2 + (size_t)h * HID * VD;
    for (int kc = 0; kc < 4; kc++) {
        __syncthreads();
        for (int idx = t; idx < 64 * VD; idx += 256)
            BUF[idx] = W2h[kc * 64 * VD + idx];           // [kk][v], stride 192
        __syncthreads();
#pragma unroll 4
        for (int kk = 0; kk < 64; kk++) {
            float p[4];
#pragma unroll
            for (int r = 0; r < 4; r++) p[r] = P_s[(ty * 4 + r) * PSTR + kc * 64 + kk];
            float w2r[12];
#pragma unroll
            for (int j = 0; j < 12; j++) w2r[j] = BUF[kk * VD + tx + 16 * j];
#pragma unroll
            for (int r = 0; r < 4; r++)
#pragma unroll
                for (int j = 0; j < 12; j++)
                    acc1[r][j] = fmaf(p[r], w2r[j], acc1[r][j]);
        }
    }
    __syncthreads();
    // attn_out (+b2) into BUF [bb][v] stride 193
#pragma unroll
    for (int r = 0; r < 4; r++)
#pragma unroll
        for (int j = 0; j < 12; j++)
            BUF[(ty * 4 + r) * 193 + tx + 16 * j] = acc1[r][j] + b2_s[tx + 16 * j];
    __syncthreads();

    // ---- Stage C: h2 = relu(attn_out @ W1o + b1o); effect = h2 . W2o ----
    float acc2[4][16] = {};
    const float* W1oh = W1o + (size_t)h * VD * HID;
    for (int vc = 0; vc < 4; vc++) {
        __syncthreads();
        for (int idx = t; idx < 48 * HID; idx += 256)
            P_s[idx] = W1oh[vc * 48 * HID + idx];         // [vv][k], stride 256
        __syncthreads();
#pragma unroll 2
        for (int vv = 0; vv < 48; vv++) {
            float av[4];
#pragma unroll
            for (int r = 0; r < 4; r++) av[r] = BUF[(ty * 4 + r) * 193 + vc * 48 + vv];
            float w1r[16];
#pragma unroll
            for (int j = 0; j < 16; j++) w1r[j] = P_s[vv * HID + tx + 16 * j];
#pragma unroll
            for (int r = 0; r < 4; r++)
#pragma unroll
                for (int j = 0; j < 16; j++)
                    acc2[r][j] = fmaf(av[r], w1r[j], acc2[r][j]);
        }
    }

    float part[4];
#pragma unroll
    for (int r = 0; r < 4; r++) {
        float s = 0.f;
#pragma unroll
        for (int j = 0; j < 16; j++) {
            int k = tx + 16 * j;
            float hv = fmaxf(acc2[r][j] + b1o_s[k], 0.f);
            s = fmaf(hv, W2o_s[k], s);
        }
        part[r] = s;
    }
#pragma unroll
    for (int o = 8; o > 0; o >>= 1)
#pragma unroll
        for (int r = 0; r < 4; r++)
            part[r] += __shfl_xor_sync(0xffffffffu, part[r], o);

    if (tx == 0) {
        float bo = b2o[h];
#pragma unroll
        for (int r = 0; r < 4; r++)
            effect[(size_t)(b0 + ty * 4 + r) * NH + h] = part[r] + bo;
    }
}

// ============================================================================
extern "C" void kernel_launch(void* const* d_in, const int* in_sizes, int n_in,
                              void* d_out, int out_size)
{
    const float* feat = (const float*)d_in[0];
    const float* act  = (const float*)d_in[1];
    const float* Wq   = (const float*)d_in[2];
    const float* bq   = (const float*)d_in[3];
    const float* Wk   = (const float*)d_in[4];
    const float* bk   = (const float*)d_in[5];
    const float* Wav  = (const float*)d_in[6];
    const float* bav  = (const float*)d_in[7];
    const float* Wfv  = (const float*)d_in[8];
    const float* bfv  = (const float*)d_in[9];
    const float* W1   = (const float*)d_in[10];
    const float* b1   = (const float*)d_in[11];
    const float* W2   = (const float*)d_in[12];
    const float* b2   = (const float*)d_in[13];
    const float* W1o  = (const float*)d_in[14];
    const float* b1o  = (const float*)d_in[15];
    const float* W2o  = (const float*)d_in[16];
    const float* b2o  = (const float*)d_in[17];

    float* out    = (float*)d_out;
    float* effect = out;                    // [B, H]
    float* attnw  = out + BATCH * NH;       // [B, H, D]

    int smem2 = (FED * 128 + DLAT * FED + FED) * 4;
    int smem4 = (DLAT * HID + HID + AED * HID + BT4 * AED + 2 * BT4 * DLAT) * 4;
    int smem5 = (BT5 * (HID + 1) + 64 * 193 + VD + HID + HID) * 4;
    cudaFuncSetAttribute(k_gpre, cudaFuncAttributeMaxDynamicSharedMemorySize, smem2);
    cudaFuncSetAttribute(k_pool, cudaFuncAttributeMaxDynamicSharedMemorySize, smem4);
    cudaFuncSetAttribute(k_out,  cudaFuncAttributeMaxDynamicSharedMemorySize, smem5);

    k_prep<<<BATCH, 192>>>(feat, act, Wq, bq, Wk, bk, Wav, bav, attnw);
    k_gpre<<<dim3(2, NH), 256, smem2>>>(Wfv, bfv, W1, b1);
    k_pool<<<dim3(BATCH / BT4, NH), 256, smem4>>>(feat, W1);
    k_out <<<dim3(BATCH / BT5, NH), 256, smem5>>>(W2, b2, W1o, b1o, W2o, b2o, effect);
}